// round 2
// baseline (speedup 1.0000x reference)
#include <cuda_runtime.h>
#include <stdint.h>

// SkipGramNS: out[i] = dot(cxt_weight[context_idxs[i]], tgt_weight[target_idxs[i]])
// N = 1e6 pairs, D = 128, V = 1e5. Tables total 102.4MB -> ~fit in GB300's ~126MB L2.
// Indices are int32 (JAX default; jnp.int64 is demoted without x64 mode).
// Strategy: one warp per pair. Lane l loads float4 #l of each 128-float row
// (fully coalesced 512B row reads), FMA, butterfly reduction, lane 0 stores.

__global__ void __launch_bounds__(256)
skipgram_dot_kernel(const int* __restrict__ ctx_idx,
                    const int* __restrict__ tgt_idx,
                    const float* __restrict__ cxt_w,
                    const float* __restrict__ tgt_w,
                    float* __restrict__ out,
                    int n)
{
    const int warp_id = (blockIdx.x * blockDim.x + threadIdx.x) >> 5;
    const int lane    = threadIdx.x & 31;
    if (warp_id >= n) return;

    const long long c = (long long)__ldg(&ctx_idx[warp_id]);
    const long long t = (long long)__ldg(&tgt_idx[warp_id]);

    const float4* __restrict__ cv =
        reinterpret_cast<const float4*>(cxt_w + c * 128);
    const float4* __restrict__ tv =
        reinterpret_cast<const float4*>(tgt_w + t * 128);

    const float4 a = __ldg(&cv[lane]);
    const float4 b = __ldg(&tv[lane]);

    float s = a.x * b.x;
    s = fmaf(a.y, b.y, s);
    s = fmaf(a.z, b.z, s);
    s = fmaf(a.w, b.w, s);

    // warp butterfly reduction
    #pragma unroll
    for (int off = 16; off > 0; off >>= 1)
        s += __shfl_xor_sync(0xFFFFFFFFu, s, off);

    if (lane == 0)
        out[warp_id] = s;
}

extern "C" void kernel_launch(void* const* d_in, const int* in_sizes, int n_in,
                              void* d_out, int out_size)
{
    const int*   ctx_idx = (const int*)d_in[0];
    const int*   tgt_idx = (const int*)d_in[1];
    const float* cxt_w   = (const float*)d_in[2];
    const float* tgt_w   = (const float*)d_in[3];
    float*       out     = (float*)d_out;

    const int n = in_sizes[0];           // 1,000,000 pairs
    const int threads = 256;             // 8 warps per block
    const int warps_per_block = threads / 32;
    const int blocks = (n + warps_per_block - 1) / warps_per_block;

    skipgram_dot_kernel<<<blocks, threads>>>(ctx_idx, tgt_idx, cxt_w, tgt_w, out, n);
}

// round 3
// speedup vs baseline: 2.0335x; 2.0335x over previous
#include <cuda_runtime.h>
#include <stdint.h>

// SkipGramNS: out[i] = dot(cxt_weight[ctx_idx[i]], tgt_weight[tgt_idx[i]])
// N=1e6, D=128, V=1e5 (tables ~102MB, mostly L2-resident on GB300's 126MB L2).
//
// R2 profile showed latency-bound (no pipe >41%, issue 27.8%). This version:
//   - 8 lanes per pair, 4 pairs per warp
//   - each lane: 4 independent float4 loads per table (MLP=8 vs 2 before)
//   - 3-step butterfly reduce within each 8-lane group
// Coalescing: within a group, lanes j=0..7 load float4[j + 8k] -> one
// contiguous 128B line per (group,k); 4 groups touch 4 rows per instruction.

__global__ void __launch_bounds__(256)
skipgram_dot_kernel(const int* __restrict__ ctx_idx,
                    const int* __restrict__ tgt_idx,
                    const float* __restrict__ cxt_w,
                    const float* __restrict__ tgt_w,
                    float* __restrict__ out,
                    int n)
{
    const int warp_id = (blockIdx.x * blockDim.x + threadIdx.x) >> 5;
    const int lane    = threadIdx.x & 31;
    const int group   = lane >> 3;   // 0..3: which pair within the warp
    const int j       = lane & 7;    // 0..7: lane within group

    const int pair = warp_id * 4 + group;
    if (pair >= n) return;

    const long long c = (long long)__ldg(&ctx_idx[pair]);
    const long long t = (long long)__ldg(&tgt_idx[pair]);

    const float4* __restrict__ cv =
        reinterpret_cast<const float4*>(cxt_w + c * 128);
    const float4* __restrict__ tv =
        reinterpret_cast<const float4*>(tgt_w + t * 128);

    // 8 independent 16B loads per lane -> high MLP
    const float4 a0 = __ldg(&cv[j]);
    const float4 a1 = __ldg(&cv[j +  8]);
    const float4 a2 = __ldg(&cv[j + 16]);
    const float4 a3 = __ldg(&cv[j + 24]);
    const float4 b0 = __ldg(&tv[j]);
    const float4 b1 = __ldg(&tv[j +  8]);
    const float4 b2 = __ldg(&tv[j + 16]);
    const float4 b3 = __ldg(&tv[j + 24]);

    float s0 = a0.x * b0.x;
    s0 = fmaf(a0.y, b0.y, s0);
    s0 = fmaf(a0.z, b0.z, s0);
    s0 = fmaf(a0.w, b0.w, s0);

    float s1 = a1.x * b1.x;
    s1 = fmaf(a1.y, b1.y, s1);
    s1 = fmaf(a1.z, b1.z, s1);
    s1 = fmaf(a1.w, b1.w, s1);

    float s2 = a2.x * b2.x;
    s2 = fmaf(a2.y, b2.y, s2);
    s2 = fmaf(a2.z, b2.z, s2);
    s2 = fmaf(a2.w, b2.w, s2);

    float s3 = a3.x * b3.x;
    s3 = fmaf(a3.y, b3.y, s3);
    s3 = fmaf(a3.z, b3.z, s3);
    s3 = fmaf(a3.w, b3.w, s3);

    float s = (s0 + s1) + (s2 + s3);

    // butterfly reduce across the 8-lane group (xor 4,2,1 stays in-group)
    s += __shfl_xor_sync(0xFFFFFFFFu, s, 4);
    s += __shfl_xor_sync(0xFFFFFFFFu, s, 2);
    s += __shfl_xor_sync(0xFFFFFFFFu, s, 1);

    if (j == 0)
        out[pair] = s;
}

extern "C" void kernel_launch(void* const* d_in, const int* in_sizes, int n_in,
                              void* d_out, int out_size)
{
    const int*   ctx_idx = (const int*)d_in[0];
    const int*   tgt_idx = (const int*)d_in[1];
    const float* cxt_w   = (const float*)d_in[2];
    const float* tgt_w   = (const float*)d_in[3];
    float*       out     = (float*)d_out;

    const int n = in_sizes[0];              // 1,000,000 pairs
    const int threads = 256;                // 8 warps/block, 32 pairs/block
    const int pairs_per_block = (threads / 32) * 4;
    const int blocks = (n + pairs_per_block - 1) / pairs_per_block;

    skipgram_dot_kernel<<<blocks, threads>>>(ctx_idx, tgt_idx, cxt_w, tgt_w, out, n);
}